// round 2
// baseline (speedup 1.0000x reference)
#include <cuda_runtime.h>
#include <math_constants.h>

// Problem constants
#define B_      4096      // batch rows (inputs)
#define N_      4096      // codebook vectors (64*64)
#define D_      512       // feature dim
#define GW      64        // grid width
// GEMM tiling
#define BM      128
#define BN      128
#define BK      16
#define TM      8
#define TN      8
#define NTHREADS 256
#define NCOLBLK (N_/BN)   // 32

// Scratch (static device globals; no runtime allocation allowed)
__device__ float g_xsq[B_];
__device__ float g_wsq[N_];
__device__ float g_pval[NCOLBLK * B_];
__device__ int   g_pidx[NCOLBLK * B_];

// ---------------------------------------------------------------------------
// Kernel 1: row sum-of-squares for inputs (x_sq) and weights (w_sq).
// One warp per row; warps 0..B_-1 -> x, B_..B_+N_-1 -> w.
// ---------------------------------------------------------------------------
__global__ void sqsum_kernel(const float* __restrict__ X,
                             const float* __restrict__ Wt) {
    int warp = (blockIdx.x * blockDim.x + threadIdx.x) >> 5;
    int lane = threadIdx.x & 31;
    if (warp >= B_ + N_) return;
    const float* src = (warp < B_) ? X : Wt;
    int row = (warp < B_) ? warp : (warp - B_);
    const float* p = src + (size_t)row * D_;
    float s = 0.f;
    #pragma unroll 4
    for (int i = lane; i < D_; i += 32) {
        float v = p[i];
        s = fmaf(v, v, s);
    }
    #pragma unroll
    for (int o = 16; o; o >>= 1) s += __shfl_xor_sync(0xffffffffu, s, o);
    if (lane == 0) {
        if (warp < B_) g_xsq[row] = s;
        else           g_wsq[row] = s;
    }
}

// ---------------------------------------------------------------------------
// Kernel 2: fp32 NT GEMM (dot = X * W^T), fused distance + per-CTA argmin.
// 128x128 tile per CTA, 8x8 per thread, BK=16, register-double-buffered LDG.
// Epilogue computes sq_dist = max((x_sq - 2*dot) + w_sq, 0) with the SAME
// rounding order as the reference, then reduces argmin (first-index ties)
// over the CTA's 128 columns and writes one partial per (colBlock,row).
// ---------------------------------------------------------------------------
__global__ __launch_bounds__(NTHREADS, 2)
void dist_argmin_kernel(const float* __restrict__ X,
                        const float* __restrict__ Wt) {
    __shared__ float As[BK][BM];
    __shared__ float Bs[BK][BN];
    __shared__ float sVal[BM][16];
    __shared__ int   sIdx[BM][16];

    const int tid = threadIdx.x;
    const int tx  = tid & 15;        // 0..15 -> col group
    const int ty  = tid >> 4;        // 0..15 -> row group
    const int rowBlk = blockIdx.y;
    const int colBlk = blockIdx.x;

    const float* Aptr = X  + (size_t)rowBlk * BM * D_;
    const float* Bptr = Wt + (size_t)colBlk * BN * D_;

    // Tile loader: 256 threads, each loads 2 float4 from A and 2 from B.
    const int lr = tid >> 2;             // 0..63 : row within tile
    const int lc = (tid & 3) * 4;        // 0,4,8,12 : k offset (float4)

    float4 ra0, ra1, rb0, rb1;
    ra0 = *(const float4*)(Aptr + (size_t)lr        * D_ + lc);
    ra1 = *(const float4*)(Aptr + (size_t)(lr + 64) * D_ + lc);
    rb0 = *(const float4*)(Bptr + (size_t)lr        * D_ + lc);
    rb1 = *(const float4*)(Bptr + (size_t)(lr + 64) * D_ + lc);

    float acc[TM][TN];
    #pragma unroll
    for (int i = 0; i < TM; i++)
        #pragma unroll
        for (int j = 0; j < TN; j++) acc[i][j] = 0.f;

    const int NKT = D_ / BK;   // 32
    for (int kt = 0; kt < NKT; kt++) {
        // commit prefetched regs into smem (transposed: [k][m])
        #pragma unroll
        for (int j = 0; j < 4; j++) {
            As[lc + j][lr]      = ((const float*)&ra0)[j];
            As[lc + j][lr + 64] = ((const float*)&ra1)[j];
            Bs[lc + j][lr]      = ((const float*)&rb0)[j];
            Bs[lc + j][lr + 64] = ((const float*)&rb1)[j];
        }
        __syncthreads();

        // prefetch next tile (LDG in flight during compute)
        if (kt + 1 < NKT) {
            int ko = (kt + 1) * BK + lc;
            ra0 = *(const float4*)(Aptr + (size_t)lr        * D_ + ko);
            ra1 = *(const float4*)(Aptr + (size_t)(lr + 64) * D_ + ko);
            rb0 = *(const float4*)(Bptr + (size_t)lr        * D_ + ko);
            rb1 = *(const float4*)(Bptr + (size_t)(lr + 64) * D_ + ko);
        }

        // FFMA mainloop
        #pragma unroll
        for (int kk = 0; kk < BK; kk++) {
            float a[TM], b[TN];
            *(float4*)&a[0] = *(const float4*)&As[kk][ty * TM];
            *(float4*)&a[4] = *(const float4*)&As[kk][ty * TM + 4];
            *(float4*)&b[0] = *(const float4*)&Bs[kk][tx * TN];
            *(float4*)&b[4] = *(const float4*)&Bs[kk][tx * TN + 4];
            #pragma unroll
            for (int i = 0; i < TM; i++)
                #pragma unroll
                for (int j = 0; j < TN; j++)
                    acc[i][j] = fmaf(a[i], b[j], acc[i][j]);
        }
        __syncthreads();
    }

    // ---- epilogue: distances + per-thread argmin over its 8 columns ----
    const int baseRow = rowBlk * BM + ty * TM;
    const int baseCol = colBlk * BN + tx * TN;

    float ws[TN];
    #pragma unroll
    for (int j = 0; j < TN; j++) ws[j] = g_wsq[baseCol + j];

    #pragma unroll
    for (int i = 0; i < TM; i++) {
        float xs = g_xsq[baseRow + i];
        float bv = CUDART_INF_F;
        int   bi = 0;
        #pragma unroll
        for (int j = 0; j < TN; j++) {
            float t = xs - 2.0f * acc[i][j];   // (x_sq - 2*dot)
            float v = t + ws[j];               // ... + w_sq   (ref rounding order)
            v = fmaxf(v, 0.0f);
            if (v < bv) { bv = v; bi = baseCol + j; }  // ascending j -> first-index ties
        }
        sVal[ty * TM + i][tx] = bv;
        sIdx[ty * TM + i][tx] = bi;
    }
    __syncthreads();

    // reduce across the 16 column groups; ascending tx preserves first-index ties
    if (tid < BM) {
        float bv = sVal[tid][0];
        int   bi = sIdx[tid][0];
        #pragma unroll
        for (int t = 1; t < 16; t++) {
            float v = sVal[tid][t];
            int   ix = sIdx[tid][t];
            if (v < bv || (v == bv && ix < bi)) { bv = v; bi = ix; }
        }
        int gr = rowBlk * BM + tid;
        g_pval[colBlk * B_ + gr] = bv;
        g_pidx[colBlk * B_ + gr] = bi;
    }
}

// ---------------------------------------------------------------------------
// Kernel 3: reduce the 32 column-block partials per row, emit outputs.
// Output layout: [B*2] bmu (y,x) as float, then [B] quantization errors.
// ---------------------------------------------------------------------------
__global__ void finalize_kernel(float* __restrict__ out) {
    int warp = (blockIdx.x * blockDim.x + threadIdx.x) >> 5;
    int lane = threadIdx.x & 31;
    if (warp >= B_) return;

    float bv = CUDART_INF_F;
    int   bi = 0x7fffffff;
    if (lane < NCOLBLK) {
        bv = g_pval[lane * B_ + warp];
        bi = g_pidx[lane * B_ + warp];
    }
    #pragma unroll
    for (int o = 16; o; o >>= 1) {
        float ov = __shfl_xor_sync(0xffffffffu, bv, o);
        int   oi = __shfl_xor_sync(0xffffffffu, bi, o);
        if (ov < bv || (ov == bv && oi < bi)) { bv = ov; bi = oi; }
    }
    if (lane == 0) {
        out[warp * 2 + 0]   = (float)(bi >> 6);    // y = n / 64
        out[warp * 2 + 1]   = (float)(bi & (GW-1));// x = n % 64
        out[2 * B_ + warp]  = sqrtf(bv);           // quantization error
    }
}

// ---------------------------------------------------------------------------
extern "C" void kernel_launch(void* const* d_in, const int* in_sizes, int n_in,
                              void* d_out, int out_size) {
    const float* X  = (const float*)d_in[0];   // inputs      (4096, 512)
    const float* Wt = (const float*)d_in[1];   // weights_map (64, 64, 512) -> (4096, 512)
    float* out = (float*)d_out;

    // 1) row sum-of-squares (8192 warps -> 1024 blocks of 8 warps)
    sqsum_kernel<<<(B_ + N_) / 8, 256>>>(X, Wt);

    // 2) fused distance GEMM + per-CTA argmin
    dim3 grid(N_ / BN, B_ / BM);   // (32, 32)
    dist_argmin_kernel<<<grid, NTHREADS>>>(X, Wt);

    // 3) final reduction + outputs (4096 warps -> 512 blocks of 8 warps)
    finalize_kernel<<<B_ / 8, 256>>>(out);
}

// round 4
// speedup vs baseline: 1.2718x; 1.2718x over previous
#include <cuda_runtime.h>
#include <cuda_bf16.h>
#include <math_constants.h>
#include <cstdint>

// Problem constants
#define B_      4096
#define N_      4096
#define D_      512
#define GW      64
#define KT2     1536          // 3 tf32 planes * 512
#define KCH     32            // K per chunk (32 fp32 = 128B rows)
#define NCH     (KT2/KCH)     // 48 chunks
#define TM_     128           // CTA M tile
#define TN_     256           // CTA N tile
#define NCOLBLK (N_/TN_)      // 16
#define NSTAGE  3
#define STAGE_BYTES 49152     // A 16KB + B 32KB
#define SM_TOTAL (NSTAGE*STAGE_BYTES)

// Scratch globals
__device__ float g_xsq[B_];
__device__ float g_wsq[N_];
__device__ float g_pval[NCOLBLK * B_];
__device__ int   g_pidx[NCOLBLK * B_];
__device__ __align__(16) float g_A[(size_t)B_ * KT2];   // 24 MB (tf32 planes)
__device__ __align__(16) float g_B[(size_t)N_ * KT2];   // 24 MB

// ---------------------------------------------------------------------------
__device__ __forceinline__ uint32_t smem_to_u32(const void* p) {
    uint32_t a;
    asm("{ .reg .u64 t; cvta.to.shared.u64 t, %1; cvt.u32.u64 %0, t; }"
        : "=r"(a) : "l"(p));
    return a;
}

#define CP_ASYNC16(dst, src) \
    asm volatile("cp.async.cg.shared.global [%0], [%1], 16;" \
        :: "r"(dst), "l"(src) : "memory")
#define CP_COMMIT()  asm volatile("cp.async.commit_group;" ::: "memory")
#define CP_WAIT1()   asm volatile("cp.async.wait_group 1;"  ::: "memory")
#define CP_WAIT0()   asm volatile("cp.async.wait_group 0;"  ::: "memory")

#define LDSM4(r0, r1, r2, r3, addr) \
    asm volatile("ldmatrix.sync.aligned.m8n8.x4.shared.b16 {%0,%1,%2,%3}, [%4];" \
        : "=r"(r0), "=r"(r1), "=r"(r2), "=r"(r3) : "r"(addr))

#define MMA_TF32(d, a, b0v, b1v) \
    asm volatile("mma.sync.aligned.m16n8k8.row.col.f32.tf32.tf32.f32 " \
        "{%0,%1,%2,%3},{%4,%5,%6,%7},{%8,%9},{%0,%1,%2,%3};" \
        : "+f"((d)[0]), "+f"((d)[1]), "+f"((d)[2]), "+f"((d)[3]) \
        : "r"((a)[0]), "r"((a)[1]), "r"((a)[2]), "r"((a)[3]), \
          "r"(b0v), "r"(b1v))

__device__ __forceinline__ float tf32_rna(float x) {
    uint32_t u;
    asm("cvt.rna.tf32.f32 %0, %1;" : "=r"(u) : "f"(x));
    return __uint_as_float(u);
}

// ---------------------------------------------------------------------------
// Kernel 0: fp32 -> tf32 split planes, concatenated along K.
// A planes: [a0, a0, a1]   B planes: [b0, b1, b0]
// sum over planes = a0b0 + a0b1 + a1b0  (error ~3*2^-23 |ab|)
// ---------------------------------------------------------------------------
__global__ void convert_kernel(const float* __restrict__ X,
                               const float* __restrict__ Wt) {
    const int t = blockIdx.y;
    const float* src = t ? Wt : X;
    float* dst = t ? g_B : g_A;
    int lin = blockIdx.x * blockDim.x + threadIdx.x;   // over 4096*512
    int row = lin >> 9;
    int k   = lin & 511;

    float a  = src[(size_t)row * D_ + k];
    float a0 = tf32_rna(a);
    float a1 = tf32_rna(a - a0);   // exact residual (Sterbenz), then tf32-round

    float* base = dst + (size_t)row * KT2 + k;
    if (t == 0) { base[0] = a0; base[512] = a0; base[1024] = a1; }
    else        { base[0] = a0; base[512] = a1; base[1024] = a0; }
}

// ---------------------------------------------------------------------------
// Kernel 1: row sum-of-squares (fp32 originals)
// ---------------------------------------------------------------------------
__global__ void sqsum_kernel(const float* __restrict__ X,
                             const float* __restrict__ Wt) {
    int warp = (blockIdx.x * blockDim.x + threadIdx.x) >> 5;
    int lane = threadIdx.x & 31;
    if (warp >= B_ + N_) return;
    const float* src = (warp < B_) ? X : Wt;
    int row = (warp < B_) ? warp : (warp - B_);
    const float* p = src + (size_t)row * D_;
    float s = 0.f;
    #pragma unroll 4
    for (int i = lane; i < D_; i += 32) { float v = p[i]; s = fmaf(v, v, s); }
    #pragma unroll
    for (int o = 16; o; o >>= 1) s += __shfl_xor_sync(0xffffffffu, s, o);
    if (lane == 0) { if (warp < B_) g_xsq[row] = s; else g_wsq[row] = s; }
}

// ---------------------------------------------------------------------------
// Kernel 2: tf32 mma.sync GEMM (M=128, N=256, K=1536) + fused argmin.
// 256 threads = 8 warps (2 m-rows x 4 n-cols), 64x64 warp tile, m16n8k8.
// 3-stage cp.async pipeline; XOR-swizzled smem; ldmatrix.x4 fragment loads.
// ---------------------------------------------------------------------------
__device__ __forceinline__ void load_stage(uint32_t sA, uint32_t sB,
                                           const float* __restrict__ gA,
                                           const float* __restrict__ gB,
                                           int arow0, int brow0, int kc0,
                                           int tid) {
    // A: 128 rows x 8 chunks(16B) = 1024 chunks
    #pragma unroll
    for (int it = 0; it < 4; it++) {
        int id = tid + it * 256;
        int m = id >> 3, ch = id & 7;
        int chs = ch ^ (m & 7);
        CP_ASYNC16(sA + m * 128 + chs * 16,
                   gA + (size_t)(arow0 + m) * KT2 + kc0 + ch * 4);
    }
    // B: 256 rows x 8 chunks = 2048 chunks
    #pragma unroll
    for (int it = 0; it < 8; it++) {
        int id = tid + it * 256;
        int n = id >> 3, ch = id & 7;
        int chs = ch ^ (n & 7);
        CP_ASYNC16(sB + n * 128 + chs * 16,
                   gB + (size_t)(brow0 + n) * KT2 + kc0 + ch * 4);
    }
}

extern "C" __global__ void __launch_bounds__(256, 1)
dist_tc_kernel() {
    extern __shared__ char smem[];
    const uint32_t sb = smem_to_u32(smem);
    const int tid = threadIdx.x;
    const int wid = tid >> 5;
    const int l   = tid & 31;
    const int rowBlk = blockIdx.y;
    const int colBlk = blockIdx.x;

    const int wm = (wid >> 2) * 64;    // warp m offset in CTA tile
    const int wn = (wid & 3) * 64;     // warp n offset

    const int arow0 = rowBlk * TM_;
    const int brow0 = colBlk * TN_;

    // ldmatrix per-lane geometry
    const int mrow = (l & 7) + ((l >> 3) & 1) * 8;   // A
    const int aAdd = l >> 4;
    const int nrow = (l & 7) + (l >> 4) * 8;         // B
    const int bAdd = (l >> 3) & 1;

    uint32_t aRowOff[4]; int aXr[4];
    #pragma unroll
    for (int i = 0; i < 4; i++) {
        int r = wm + i * 16 + mrow;
        aRowOff[i] = r * 128; aXr[i] = r & 7;
    }
    uint32_t bRowOff[4]; int bXr[4];
    #pragma unroll
    for (int jj = 0; jj < 4; jj++) {
        int r = wn + jj * 16 + nrow;
        bRowOff[jj] = r * 128; bXr[jj] = r & 7;
    }

    float acc[4][8][4];
    #pragma unroll
    for (int i = 0; i < 4; i++)
        #pragma unroll
        for (int j = 0; j < 8; j++)
            #pragma unroll
            for (int q = 0; q < 4; q++) acc[i][j][q] = 0.f;

    // prologue: stages 0, 1
    load_stage(sb, sb + 16384, g_A, g_B, arow0, brow0, 0, tid);
    CP_COMMIT();
    load_stage(sb + STAGE_BYTES, sb + STAGE_BYTES + 16384,
               g_A, g_B, arow0, brow0, KCH, tid);
    CP_COMMIT();

    for (int c = 0; c < NCH; c++) {
        CP_WAIT1();
        __syncthreads();

        if (c + 2 < NCH) {
            uint32_t st = sb + ((c + 2) % NSTAGE) * STAGE_BYTES;
            load_stage(st, st + 16384, g_A, g_B, arow0, brow0, (c + 2) * KCH, tid);
        }
        CP_COMMIT();

        const uint32_t Ab = sb + (c % NSTAGE) * STAGE_BYTES;
        const uint32_t Bb = Ab + 16384;

        #pragma unroll
        for (int ks = 0; ks < 4; ks++) {
            uint32_t ar[4][4];
            #pragma unroll
            for (int i = 0; i < 4; i++)
                LDSM4(ar[i][0], ar[i][1], ar[i][2], ar[i][3],
                      Ab + aRowOff[i] + (uint32_t)(((ks * 2 + aAdd) ^ aXr[i]) * 16));
            uint32_t br[8][2];
            #pragma unroll
            for (int jj = 0; jj < 4; jj++) {
                uint32_t r0, r1, r2, r3;
                LDSM4(r0, r1, r2, r3,
                      Bb + bRowOff[jj] + (uint32_t)(((ks * 2 + bAdd) ^ bXr[jj]) * 16));
                br[jj * 2][0] = r0;  br[jj * 2][1] = r1;
                br[jj * 2 + 1][0] = r2;  br[jj * 2 + 1][1] = r3;
            }
            #pragma unroll
            for (int i = 0; i < 4; i++)
                #pragma unroll
                for (int j = 0; j < 8; j++)
                    MMA_TF32(acc[i][j], ar[i], br[j][0], br[j][1]);
        }
    }
    CP_WAIT0();
    __syncthreads();

    // ---- epilogue: distances + argmin over the CTA's 256 columns ----
    // acc[i][j]: d0 (row l>>2,      col (l&3)*2),   d1 (.., col+1),
    //            d2 (row l>>2 + 8,  col (l&3)*2),   d3 (.., col+1)
    const int cbase = colBlk * TN_ + wn;
    float ws[8][2];
    #pragma unroll
    for (int j = 0; j < 8; j++) {
        ws[j][0] = g_wsq[cbase + j * 8 + (l & 3) * 2];
        ws[j][1] = g_wsq[cbase + j * 8 + (l & 3) * 2 + 1];
    }

    float* sVal = (float*)smem;            // [128][4]
    int*   sIdx = (int*)(smem + 2048);     // [128][4]

    #pragma unroll
    for (int i = 0; i < 4; i++) {
        #pragma unroll
        for (int h = 0; h < 2; h++) {
            int lrow = wm + i * 16 + h * 8 + (l >> 2);
            float xs = g_xsq[arow0 + lrow];
            float bv = CUDART_INF_F;
            int   bi = 0;
            #pragma unroll
            for (int j = 0; j < 8; j++) {
                #pragma unroll
                for (int q = 0; q < 2; q++) {
                    int col = cbase + j * 8 + (l & 3) * 2 + q;
                    float dot = acc[i][j][h * 2 + q];
                    float v = fmaxf((xs - 2.0f * dot) + ws[j][q], 0.0f);
                    if (v < bv) { bv = v; bi = col; }
                }
            }
            // reduce across the 4 lanes sharing this row (l&3 varies)
            #pragma unroll
            for (int o = 1; o <= 2; o <<= 1) {
                float ov = __shfl_xor_sync(0xffffffffu, bv, o);
                int   oi = __shfl_xor_sync(0xffffffffu, bi, o);
                if (ov < bv || (ov == bv && oi < bi)) { bv = ov; bi = oi; }
            }
            if ((l & 3) == 0) {
                sVal[lrow * 4 + (wid & 3)] = bv;
                sIdx[lrow * 4 + (wid & 3)] = bi;
            }
        }
    }
    __syncthreads();

    if (tid < TM_) {
        float bv = sVal[tid * 4];
        int   bi = sIdx[tid * 4];
        #pragma unroll
        for (int t = 1; t < 4; t++) {
            float v = sVal[tid * 4 + t];
            int   ix = sIdx[tid * 4 + t];
            if (v < bv || (v == bv && ix < bi)) { bv = v; bi = ix; }
        }
        int gr = arow0 + tid;
        g_pval[colBlk * B_ + gr] = bv;
        g_pidx[colBlk * B_ + gr] = bi;
    }
}

// ---------------------------------------------------------------------------
// Kernel 3: reduce the 16 column-block partials per row, emit outputs.
// ---------------------------------------------------------------------------
__global__ void finalize_kernel(float* __restrict__ out) {
    int warp = (blockIdx.x * blockDim.x + threadIdx.x) >> 5;
    int lane = threadIdx.x & 31;
    if (warp >= B_) return;

    float bv = CUDART_INF_F;
    int   bi = 0x7fffffff;
    if (lane < NCOLBLK) {
        bv = g_pval[lane * B_ + warp];
        bi = g_pidx[lane * B_ + warp];
    }
    #pragma unroll
    for (int o = 16; o; o >>= 1) {
        float ov = __shfl_xor_sync(0xffffffffu, bv, o);
        int   oi = __shfl_xor_sync(0xffffffffu, bi, o);
        if (ov < bv || (ov == bv && oi < bi)) { bv = ov; bi = oi; }
    }
    if (lane == 0) {
        out[warp * 2 + 0]  = (float)(bi >> 6);
        out[warp * 2 + 1]  = (float)(bi & (GW - 1));
        out[2 * B_ + warp] = sqrtf(bv);
    }
}

// ---------------------------------------------------------------------------
extern "C" void kernel_launch(void* const* d_in, const int* in_sizes, int n_in,
                              void* d_out, int out_size) {
    const float* X  = (const float*)d_in[0];
    const float* Wt = (const float*)d_in[1];
    float* out = (float*)d_out;

    cudaFuncSetAttribute(dist_tc_kernel,
                         cudaFuncAttributeMaxDynamicSharedMemorySize, SM_TOTAL);

    // 0) tf32 split planes
    dim3 cgrid(B_ * D_ / 256, 2);
    convert_kernel<<<cgrid, 256>>>(X, Wt);

    // 1) row sum-of-squares
    sqsum_kernel<<<(B_ + N_) / 8, 256>>>(X, Wt);

    // 2) tensor-core distance GEMM + per-tile argmin
    dim3 grid(N_ / TN_, B_ / TM_);   // (16, 32)
    dist_tc_kernel<<<grid, 256, SM_TOTAL>>>();

    // 3) final reduction + outputs
    finalize_kernel<<<B_ / 8, 256>>>(out);
}

// round 6
// speedup vs baseline: 1.5312x; 1.2040x over previous
#include <cuda_runtime.h>
#include <cuda_bf16.h>
#include <math_constants.h>
#include <cstdint>

// Problem constants
#define B_      4096
#define N_      4096
#define D_      512
#define GW      64
#define KT2     1536          // 3 tf32 planes * 512
#define KCH     32            // K per chunk (32 fp32 = 128B rows)
#define NCH     (KT2/KCH)     // 48 chunks
#define TM_     128           // CTA M tile
#define TN_     128           // CTA N tile
#define NCOLBLK (N_/TN_)      // 32
#define NSTAGE  3
#define STAGE_BYTES 32768     // A 16KB + B 16KB
#define SM_TOTAL (NSTAGE*STAGE_BYTES)   // 96 KB -> 2 CTAs/SM

// Scratch globals
__device__ float g_xsq[B_];
__device__ float g_wsq[N_];
__device__ float g_pval[NCOLBLK * B_];
__device__ int   g_pidx[NCOLBLK * B_];
__device__ __align__(16) float g_A[(size_t)B_ * KT2];   // 24 MB (tf32 planes)
__device__ __align__(16) float g_B[(size_t)N_ * KT2];   // 24 MB

// ---------------------------------------------------------------------------
__device__ __forceinline__ uint32_t smem_to_u32(const void* p) {
    uint32_t a;
    asm("{ .reg .u64 t; cvta.to.shared.u64 t, %1; cvt.u32.u64 %0, t; }"
        : "=r"(a) : "l"(p));
    return a;
}

#define CP_ASYNC16(dst, src) \
    asm volatile("cp.async.cg.shared.global [%0], [%1], 16;" \
        :: "r"(dst), "l"(src) : "memory")
#define CP_COMMIT()  asm volatile("cp.async.commit_group;" ::: "memory")
#define CP_WAIT1()   asm volatile("cp.async.wait_group 1;"  ::: "memory")
#define CP_WAIT0()   asm volatile("cp.async.wait_group 0;"  ::: "memory")

#define LDSM4(r0, r1, r2, r3, addr) \
    asm volatile("ldmatrix.sync.aligned.m8n8.x4.shared.b16 {%0,%1,%2,%3}, [%4];" \
        : "=r"(r0), "=r"(r1), "=r"(r2), "=r"(r3) : "r"(addr))

#define MMA_TF32(d, a, b0v, b1v) \
    asm volatile("mma.sync.aligned.m16n8k8.row.col.f32.tf32.tf32.f32 " \
        "{%0,%1,%2,%3},{%4,%5,%6,%7},{%8,%9},{%0,%1,%2,%3};" \
        : "+f"((d)[0]), "+f"((d)[1]), "+f"((d)[2]), "+f"((d)[3]) \
        : "r"((a)[0]), "r"((a)[1]), "r"((a)[2]), "r"((a)[3]), \
          "r"(b0v), "r"(b1v))

__device__ __forceinline__ float tf32_rna(float x) {
    uint32_t u;
    asm("cvt.rna.tf32.f32 %0, %1;" : "=r"(u) : "f"(x));
    return __uint_as_float(u);
}

// ---------------------------------------------------------------------------
// Kernel 0: fp32 -> tf32 split planes, concatenated along K.
// A planes: [a0, a0, a1]   B planes: [b0, b1, b0]
// ---------------------------------------------------------------------------
__global__ void convert_kernel(const float* __restrict__ X,
                               const float* __restrict__ Wt) {
    const int t = blockIdx.y;
    const float* src = t ? Wt : X;
    float* dst = t ? g_B : g_A;
    int lin = blockIdx.x * blockDim.x + threadIdx.x;
    int row = lin >> 9;
    int k   = lin & 511;

    float a  = src[(size_t)row * D_ + k];
    float a0 = tf32_rna(a);
    float a1 = tf32_rna(a - a0);

    float* base = dst + (size_t)row * KT2 + k;
    if (t == 0) { base[0] = a0; base[512] = a0; base[1024] = a1; }
    else        { base[0] = a0; base[512] = a1; base[1024] = a0; }
}

// ---------------------------------------------------------------------------
// Kernel 1: row sum-of-squares (fp32 originals)
// ---------------------------------------------------------------------------
__global__ void sqsum_kernel(const float* __restrict__ X,
                             const float* __restrict__ Wt) {
    int warp = (blockIdx.x * blockDim.x + threadIdx.x) >> 5;
    int lane = threadIdx.x & 31;
    if (warp >= B_ + N_) return;
    const float* src = (warp < B_) ? X : Wt;
    int row = (warp < B_) ? warp : (warp - B_);
    const float* p = src + (size_t)row * D_;
    float s = 0.f;
    #pragma unroll 4
    for (int i = lane; i < D_; i += 32) { float v = p[i]; s = fmaf(v, v, s); }
    #pragma unroll
    for (int o = 16; o; o >>= 1) s += __shfl_xor_sync(0xffffffffu, s, o);
    if (lane == 0) { if (warp < B_) g_xsq[row] = s; else g_wsq[row] = s; }
}

// ---------------------------------------------------------------------------
// Kernel 2: tf32 mma.sync GEMM (M=128, N=128, K=1536) + fused argmin.
// 256 threads = 8 warps (2 m-rows x 4 n-cols), 64x32 warp tile, m16n8k8.
// 3-stage cp.async pipeline, 2 CTAs/SM.
// ---------------------------------------------------------------------------
__device__ __forceinline__ void load_stage(uint32_t sA, uint32_t sB,
                                           const float* __restrict__ gA,
                                           const float* __restrict__ gB,
                                           int arow0, int brow0, int kc0,
                                           int tid) {
    // A: 128 rows x 8 chunks(16B) = 1024 chunks
    #pragma unroll
    for (int it = 0; it < 4; it++) {
        int id = tid + it * 256;
        int m = id >> 3, ch = id & 7;
        int chs = ch ^ (m & 7);
        CP_ASYNC16(sA + m * 128 + chs * 16,
                   gA + (size_t)(arow0 + m) * KT2 + kc0 + ch * 4);
    }
    // B: 128 rows x 8 chunks = 1024 chunks
    #pragma unroll
    for (int it = 0; it < 4; it++) {
        int id = tid + it * 256;
        int n = id >> 3, ch = id & 7;
        int chs = ch ^ (n & 7);
        CP_ASYNC16(sB + n * 128 + chs * 16,
                   gB + (size_t)(brow0 + n) * KT2 + kc0 + ch * 4);
    }
}

extern "C" __global__ void __launch_bounds__(256, 2)
dist_tc_kernel() {
    extern __shared__ char smem[];
    const uint32_t sb = smem_to_u32(smem);
    const int tid = threadIdx.x;
    const int wid = tid >> 5;
    const int l   = tid & 31;
    const int rowBlk = blockIdx.y;
    const int colBlk = blockIdx.x;

    const int wm = (wid >> 2) * 64;    // warp m offset (0 / 64)
    const int wn = (wid & 3) * 32;     // warp n offset (0..96)

    const int arow0 = rowBlk * TM_;
    const int brow0 = colBlk * TN_;

    // ldmatrix per-lane geometry
    const int mrow = (l & 7) + ((l >> 3) & 1) * 8;   // A
    const int aAdd = l >> 4;
    const int nrow = (l & 7) + (l >> 4) * 8;         // B
    const int bAdd = (l >> 3) & 1;

    uint32_t aRowOff[4]; int aXr[4];
    #pragma unroll
    for (int i = 0; i < 4; i++) {
        int r = wm + i * 16 + mrow;
        aRowOff[i] = r * 128; aXr[i] = r & 7;
    }
    uint32_t bRowOff[2]; int bXr[2];
    #pragma unroll
    for (int jj = 0; jj < 2; jj++) {
        int r = wn + jj * 16 + nrow;
        bRowOff[jj] = r * 128; bXr[jj] = r & 7;
    }

    float acc[4][4][4];
    #pragma unroll
    for (int i = 0; i < 4; i++)
        #pragma unroll
        for (int j = 0; j < 4; j++)
            #pragma unroll
            for (int q = 0; q < 4; q++) acc[i][j][q] = 0.f;

    // prologue: stages 0, 1
    load_stage(sb, sb + 16384, g_A, g_B, arow0, brow0, 0, tid);
    CP_COMMIT();
    load_stage(sb + STAGE_BYTES, sb + STAGE_BYTES + 16384,
               g_A, g_B, arow0, brow0, KCH, tid);
    CP_COMMIT();

    for (int c = 0; c < NCH; c++) {
        CP_WAIT1();
        __syncthreads();

        if (c + 2 < NCH) {
            uint32_t st = sb + ((c + 2) % NSTAGE) * STAGE_BYTES;
            load_stage(st, st + 16384, g_A, g_B, arow0, brow0, (c + 2) * KCH, tid);
        }
        CP_COMMIT();

        const uint32_t Ab = sb + (c % NSTAGE) * STAGE_BYTES;
        const uint32_t Bb = Ab + 16384;

        #pragma unroll
        for (int ks = 0; ks < 4; ks++) {
            uint32_t ar[4][4];
            #pragma unroll
            for (int i = 0; i < 4; i++)
                LDSM4(ar[i][0], ar[i][1], ar[i][2], ar[i][3],
                      Ab + aRowOff[i] + (uint32_t)(((ks * 2 + aAdd) ^ aXr[i]) * 16));
            uint32_t br[4][2];
            #pragma unroll
            for (int jj = 0; jj < 2; jj++) {
                uint32_t r0, r1, r2, r3;
                LDSM4(r0, r1, r2, r3,
                      Bb + bRowOff[jj] + (uint32_t)(((ks * 2 + bAdd) ^ bXr[jj]) * 16));
                br[jj * 2][0] = r0;      br[jj * 2][1] = r1;
                br[jj * 2 + 1][0] = r2;  br[jj * 2 + 1][1] = r3;
            }
            #pragma unroll
            for (int i = 0; i < 4; i++)
                #pragma unroll
                for (int j = 0; j < 4; j++)
                    MMA_TF32(acc[i][j], ar[i], br[j][0], br[j][1]);
        }
    }
    CP_WAIT0();
    __syncthreads();

    // ---- epilogue: distances + argmin over the CTA's 128 columns ----
    const int cbase = colBlk * TN_ + wn;
    float ws[4][2];
    #pragma unroll
    for (int j = 0; j < 4; j++) {
        ws[j][0] = g_wsq[cbase + j * 8 + (l & 3) * 2];
        ws[j][1] = g_wsq[cbase + j * 8 + (l & 3) * 2 + 1];
    }

    float* sVal = (float*)smem;            // [128][4]
    int*   sIdx = (int*)(smem + 2048);     // [128][4]

    #pragma unroll
    for (int i = 0; i < 4; i++) {
        #pragma unroll
        for (int h = 0; h < 2; h++) {
            int lrow = wm + i * 16 + h * 8 + (l >> 2);
            float xs = g_xsq[arow0 + lrow];
            float bv = CUDART_INF_F;
            int   bi = 0;
            #pragma unroll
            for (int j = 0; j < 4; j++) {
                #pragma unroll
                for (int q = 0; q < 2; q++) {
                    int col = cbase + j * 8 + (l & 3) * 2 + q;
                    float dot = acc[i][j][h * 2 + q];
                    float v = fmaxf((xs - 2.0f * dot) + ws[j][q], 0.0f);
                    if (v < bv) { bv = v; bi = col; }
                }
            }
            #pragma unroll
            for (int o = 1; o <= 2; o <<= 1) {
                float ov = __shfl_xor_sync(0xffffffffu, bv, o);
                int   oi = __shfl_xor_sync(0xffffffffu, bi, o);
                if (ov < bv || (ov == bv && oi < bi)) { bv = ov; bi = oi; }
            }
            if ((l & 3) == 0) {
                sVal[lrow * 4 + (wid & 3)] = bv;
                sIdx[lrow * 4 + (wid & 3)] = bi;
            }
        }
    }
    __syncthreads();

    if (tid < TM_) {
        float bv = sVal[tid * 4];
        int   bi = sIdx[tid * 4];
        #pragma unroll
        for (int t = 1; t < 4; t++) {
            float v = sVal[tid * 4 + t];
            int   ix = sIdx[tid * 4 + t];
            if (v < bv || (v == bv && ix < bi)) { bv = v; bi = ix; }
        }
        int gr = arow0 + tid;
        g_pval[colBlk * B_ + gr] = bv;
        g_pidx[colBlk * B_ + gr] = bi;
    }
}

// ---------------------------------------------------------------------------
// Kernel 3: reduce the 32 column-block partials per row, emit outputs.
// ---------------------------------------------------------------------------
__global__ void finalize_kernel(float* __restrict__ out) {
    int warp = (blockIdx.x * blockDim.x + threadIdx.x) >> 5;
    int lane = threadIdx.x & 31;
    if (warp >= B_) return;

    float bv = g_pval[lane * B_ + warp];
    int   bi = g_pidx[lane * B_ + warp];
    #pragma unroll
    for (int o = 16; o; o >>= 1) {
        float ov = __shfl_xor_sync(0xffffffffu, bv, o);
        int   oi = __shfl_xor_sync(0xffffffffu, bi, o);
        if (ov < bv || (ov == bv && oi < bi)) { bv = ov; bi = oi; }
    }
    if (lane == 0) {
        out[warp * 2 + 0]  = (float)(bi >> 6);
        out[warp * 2 + 1]  = (float)(bi & (GW - 1));
        out[2 * B_ + warp] = sqrtf(bv);
    }
}

// ---------------------------------------------------------------------------
extern "C" void kernel_launch(void* const* d_in, const int* in_sizes, int n_in,
                              void* d_out, int out_size) {
    const float* X  = (const float*)d_in[0];
    const float* Wt = (const float*)d_in[1];
    float* out = (float*)d_out;

    cudaFuncSetAttribute(dist_tc_kernel,
                         cudaFuncAttributeMaxDynamicSharedMemorySize, SM_TOTAL);

    // 0) tf32 split planes
    dim3 cgrid(B_ * D_ / 256, 2);
    convert_kernel<<<cgrid, 256>>>(X, Wt);

    // 1) row sum-of-squares
    sqsum_kernel<<<(B_ + N_) / 8, 256>>>(X, Wt);

    // 2) tensor-core distance GEMM + per-tile argmin
    dim3 grid(N_ / TN_, B_ / TM_);   // (32, 32) = 1024 CTAs, 2/SM
    dist_tc_kernel<<<grid, 256, SM_TOTAL>>>();

    // 3) final reduction + outputs
    finalize_kernel<<<B_ / 8, 256>>>(out);
}